// round 12
// baseline (speedup 1.0000x reference)
#include <cuda_runtime.h>
#include <cuda_bf16.h>
#include <cuda_fp16.h>

#define NN      50000
#define EE      800000
#define ET      (EE + NN)      // edges incl. self loops
#define NG      512
#define FIN     128
#define FH      64
#define NCLS    10
#define NEGS    0.2f
#define EPSV    1e-16f
#define NBLK    ((NN + 255) / 256)   // 196 scan blocks

// ---------------- device scratch (no allocations allowed) ----------------
// INVARIANT: g_deg and g_pool are all-zero at every kernel_launch entry.
// (zero at module load; k_scatter re-zeroes g_deg, k_final re-zeroes g_pool.)
__device__ __half g_h[NN * FH];       // pre-aggregation features (fp16 gather payload)
__device__ float  g_x2[NN * FH];      // layer-1 output / layer-2 input
__device__ float  g_as[NN];           // alpha_src per node
__device__ float  g_ad[NN];           // alpha_dst per node
__device__ int    g_deg[NN];          // real in-degree only (self loop added in scan)
__device__ int    g_off[NN + 1];
__device__ int    g_cur[NN];
__device__ int    g_csrc[ET];         // CSR (by dst): source node ids
__device__ float  g_pool[NG * FH];
__device__ int    g_bnd[NG + 1];

// per-warp dtype detection from edge_index (values < NN; int32 data read as
// int64 yields huge values from packed pairs). batch can't be used: sorted,
// starts at 0, would false-positive as int64.
__device__ __forceinline__ int warp_is64(const void* ei) {
    const long long* p = (const long long*)ei;
    long long v = p[threadIdx.x & 31];
    int bad = (v < 0 || v >= NN);
    return (__ballot_sync(0xffffffffu, bad) == 0u);
}
__device__ __forceinline__ int ld_idx(const void* p, long i, int is64) {
    if (is64) return (int)((const long long*)p)[i];
    return ((const int*)p)[i];
}

// ---- packed f32x2 helpers (Blackwell FFMA2: 2x fp32 throughput) ----
__device__ __forceinline__ void ffma2(unsigned long long& acc,
                                      unsigned long long a, unsigned long long b) {
    asm("fma.rn.f32x2 %0, %1, %2, %0;" : "+l"(acc) : "l"(a), "l"(b));
}
__device__ __forceinline__ void upk(unsigned long long r, float& a, float& b) {
    asm("mov.b64 {%0,%1}, %2;" : "=f"(a), "=f"(b) : "l"(r));
}

// ---------------- merged exclusive scan of (deg+1) -------------------------
// Each block sums g_deg over [0, blk*256) itself (coalesced, L1/L2-resident,
// fully parallel across blocks) — no separate block-sums kernel/launch.
// NOTE: cross-block reads mean g_deg must NOT be zeroed here (done in scatter).
__global__ void k_scan() {
    __shared__ int ws[8];
    __shared__ int boff_s;
    int tid = threadIdx.x, lane = tid & 31, wid = tid >> 5;
    int pre = blockIdx.x * 256;       // elements before this block

    // prefix sum of preceding degs (4 independent load chains)
    int a0 = 0, a1 = 0, a2 = 0, a3 = 0;
    int j = tid;
    for (; j + 768 < pre; j += 1024) {
        a0 += g_deg[j];
        a1 += g_deg[j + 256];
        a2 += g_deg[j + 512];
        a3 += g_deg[j + 768];
    }
    for (; j < pre; j += 256) a0 += g_deg[j];
    int acc = (a0 + a1) + (a2 + a3);
    #pragma unroll
    for (int off = 16; off > 0; off >>= 1) acc += __shfl_xor_sync(0xffffffffu, acc, off);
    if (lane == 0) ws[wid] = acc;
    __syncthreads();
    if (tid == 0) {
        int s = 0;
        #pragma unroll
        for (int q = 0; q < 8; q++) s += ws[q];
        boff_s = s + pre;             // + pre accounts for the +1 self loop each
    }
    __syncthreads();
    int boff = boff_s;
    __syncthreads();                  // ws reused below

    // local exclusive scan of this block's (deg+1)
    int i = pre + tid;
    int v = (i < NN) ? (g_deg[i] + 1) : 0;
    int val = v;
    #pragma unroll
    for (int off = 1; off < 32; off <<= 1) {
        int t = __shfl_up_sync(0xffffffffu, val, off);
        if (lane >= off) val += t;
    }
    if (lane == 31) ws[wid] = val;
    __syncthreads();
    if (wid == 0 && lane < 8) {
        int s = ws[lane];
        #pragma unroll
        for (int off = 1; off < 8; off <<= 1) {
            int t = __shfl_up_sync(0xffu, s, off);
            if (lane >= off) s += t;
        }
        ws[lane] = s;
    }
    __syncthreads();
    int woff = (wid > 0) ? ws[wid - 1] : 0;
    int excl = val - v + woff + boff;
    if (i < NN) { g_off[i] = excl; g_cur[i] = excl; }
    if (i == NN - 1) g_off[NN] = ET;
}

// ---------------- scatter edges (+self loops) into CSR ---------------------
// Phase-split for MLP: batch loads -> batch atomics -> batch stores.
// Also re-zeroes g_deg (all k_scan blocks are done by now).
#define ST ((ET + 3) / 4)      // 212513; quarters tile exactly with guard
__global__ void k_scatter(const void* __restrict__ ei) {
    int is64 = warp_is64(ei);
    int t = blockIdx.x * blockDim.x + threadIdx.x;
    if (t >= ST) return;
    if (t < NN) g_deg[t] = 0;         // re-arm invariant for next call

    int d[4], s[4];
    bool ok[4];
    #pragma unroll
    for (int q = 0; q < 4; q++) {     // batch loads (independent)
        int i = t + q * ST;
        ok[q] = (i < ET);
        d[q] = 0; s[q] = 0;
        if (i < EE) {
            d[q] = ld_idx(ei, (long)EE + i, is64);
            s[q] = ld_idx(ei, i, is64);
        } else if (i < ET) {
            d[q] = i - EE;
            s[q] = i - EE;
        }
    }
    int pos[4];
    #pragma unroll
    for (int q = 0; q < 4; q++)       // batch atomics (pipeline)
        if (ok[q]) pos[q] = atomicAdd(&g_cur[d[q]], 1);
    #pragma unroll
    for (int q = 0; q < 4; q++)       // batch stores
        if (ok[q]) g_csrc[pos[q]] = s[q];
}

// ---------------- linear: g_h = x @ W ; g_as = h.a_src ; g_ad = h.a_dst ----
// Compute fp32 (f32x2 packed FMAs); store h as fp16 for the gather.
// XTRA==1: also histogram edge in-degrees (fire-and-forget REDs hide under GEMM).
// XTRA==2: also mark graph boundaries from sorted batch.
template <int K, int SRC, int XTRA>
__global__ void __launch_bounds__(128) k_lin(const float* __restrict__ x,
                                             const float* __restrict__ W,
                                             const float* __restrict__ a_s,
                                             const float* __restrict__ a_d,
                                             const void* __restrict__ ei,
                                             const void* __restrict__ batch) {
    constexpr int KP = K + 4;                 // pad: (c*KP) % 32 walks banks
    __shared__ float Wt[FH * KP];             // W transposed: Wt[c][k]
    __shared__ float xs[32 * K];
    int tid = threadIdx.x;

    if (XTRA == 1) {                  // fused degree histogram (512 edges/block)
        int is64 = warp_is64(ei);
        int ebase = blockIdx.x * 512;
        #pragma unroll
        for (int q = 0; q < 4; q++) {
            int e = ebase + tid + q * 128;
            if (e < EE) {
                int dd = ld_idx(ei, (long)EE + e, is64);
                atomicAdd(&g_deg[dd], 1);     // no return use -> RED
            }
        }
    }
    if (XTRA == 2) {                  // fused graph-boundary marking
        int is64 = warp_is64(ei);
        int i = blockIdx.x * 128 + tid;
        if (i < NN) {
            int b  = ld_idx(batch, i, is64);
            int bp = (i == 0) ? -1 : ld_idx(batch, i - 1, is64);
            for (int g = bp + 1; g <= b; g++) g_bnd[g] = i;
            if (i == NN - 1)
                for (int g = b + 1; g <= NG; g++) g_bnd[g] = NN;
        }
    }

    for (int i = tid; i < K * FH; i += 128) {
        int k = i / FH, c = i % FH;
        Wt[c * KP + k] = W[i];
    }
    int base = blockIdx.x * 32;
    const float* xin = (SRC == 0) ? x : (const float*)g_x2;
    for (int i = tid; i < 32 * K; i += 128) {
        int n = i / K;
        int node = base + n;
        xs[i] = (node < NN) ? xin[(size_t)node * K + (i % K)] : 0.f;
    }
    __syncthreads();

    int c = tid & 31;       // output cols c and c+32
    int w = tid >> 5;       // warp handles nodes base + w*8 .. +7

    unsigned long long accA[8][2], accB[8][2];
    #pragma unroll
    for (int n = 0; n < 8; n++) {
        accA[n][0] = accA[n][1] = 0ull;
        accB[n][0] = accB[n][1] = 0ull;
    }

    const ulonglong2* wrowA = (const ulonglong2*)(Wt + c * KP);
    const ulonglong2* wrowB = (const ulonglong2*)(Wt + (c + 32) * KP);
    const ulonglong2* xrow  = (const ulonglong2*)(xs + (w * 8) * K);

    #pragma unroll 4
    for (int k4 = 0; k4 < K / 4; k4++) {
        ulonglong2 wa = wrowA[k4];
        ulonglong2 wb = wrowB[k4];
        #pragma unroll
        for (int n = 0; n < 8; n++) {
            ulonglong2 xv = xrow[n * (K / 4) + k4];   // broadcast across lanes
            ffma2(accA[n][0], xv.x, wa.x);
            ffma2(accA[n][1], xv.y, wa.y);
            ffma2(accB[n][0], xv.x, wb.x);
            ffma2(accB[n][1], xv.y, wb.y);
        }
    }

    float as0 = a_s[c], as1 = a_s[32 + c];
    float ad0 = a_d[c], ad1 = a_d[32 + c];
    #pragma unroll
    for (int n = 0; n < 8; n++) {
        int node = base + w * 8 + n;
        float p0, p1, p2, p3;
        upk(accA[n][0], p0, p1); upk(accA[n][1], p2, p3);
        float h0 = (p0 + p1) + (p2 + p3);
        upk(accB[n][0], p0, p1); upk(accB[n][1], p2, p3);
        float h1 = (p0 + p1) + (p2 + p3);
        if (node < NN) {
            g_h[node * FH + c]      = __float2half_rn(h0);
            g_h[node * FH + 32 + c] = __float2half_rn(h1);
        }
        float s = h0 * as0 + h1 * as1;
        float d = h0 * ad0 + h1 * ad1;
        #pragma unroll
        for (int off = 16; off > 0; off >>= 1) {
            s += __shfl_xor_sync(0xffffffffu, s, off);
            d += __shfl_xor_sync(0xffffffffu, d, off);
        }
        if (c == 0 && node < NN) { g_as[node] = s; g_ad[node] = d; }
    }
}

// ---------------- GAT gather: warp per node, single pass -------------------
// exp without max-subtraction: logits O(+-10), safe in fp32, identical math:
// out = sum(e_i*h_i) / (sum e_i + EPS). 8-edge batches -> 8 independent LDGs.
template <int LAYER>
__global__ void __launch_bounds__(256) k_gat(const float* __restrict__ b,
                                             const void* __restrict__ batch,
                                             const void* __restrict__ ei) {
    int lane = threadIdx.x & 31;
    int w = threadIdx.x >> 5;
    int node = blockIdx.x * 8 + w;        // NN % 8 == 0
    int beg = g_off[node];
    int end = g_off[node + 1];
    float adv = g_ad[node];

    const __half2* h2 = (const __half2*)g_h;
    float2 acc = make_float2(0.f, 0.f);
    float esum = 0.f;
    for (int cb = beg; cb < end; cb += 32) {
        int i = cb + lane;
        int s = 0; float e = 0.f;
        if (i < end) {
            s = g_csrc[i];
            float l = g_as[s] + adv;
            l = (l > 0.f) ? l : NEGS * l;
            e = __expf(l);
        }
        esum += e;
        int cnt = min(32, end - cb);
        int j = 0;
        for (; j + 8 <= cnt; j += 8) {
            float wj[8]; int sj[8]; float2 hv[8];
            #pragma unroll
            for (int q = 0; q < 8; q++) {
                wj[q] = __shfl_sync(0xffffffffu, e, j + q);
                sj[q] = __shfl_sync(0xffffffffu, s, j + q);
            }
            #pragma unroll
            for (int q = 0; q < 8; q++)
                hv[q] = __half22float2(h2[sj[q] * 32 + lane]);
            #pragma unroll
            for (int q = 0; q < 8; q++) {
                acc.x = fmaf(wj[q], hv[q].x, acc.x);
                acc.y = fmaf(wj[q], hv[q].y, acc.y);
            }
        }
        for (; j < cnt; j++) {
            float wj = __shfl_sync(0xffffffffu, e, j);
            int   sj = __shfl_sync(0xffffffffu, s, j);
            float2 hv = __half22float2(h2[sj * 32 + lane]);
            acc.x = fmaf(wj, hv.x, acc.x);
            acc.y = fmaf(wj, hv.y, acc.y);
        }
    }
    #pragma unroll
    for (int off = 16; off > 0; off >>= 1)
        esum += __shfl_xor_sync(0xffffffffu, esum, off);
    float inv = 1.f / (esum + EPSV);

    float v0 = acc.x * inv + b[2 * lane];
    float v1 = acc.y * inv + b[2 * lane + 1];

    if (LAYER == 1) {
        v0 = fmaxf(v0, 0.f);
        v1 = fmaxf(v1, 0.f);
        ((float2*)g_x2)[node * 32 + lane] = make_float2(v0, v1);
    } else {
        int is64 = warp_is64(ei);
        __shared__ float sv[8][FH];
        __shared__ int sg[8];
        sv[w][2 * lane]     = v0;
        sv[w][2 * lane + 1] = v1;
        if (lane == 0) sg[w] = ld_idx(batch, node, is64);
        __syncthreads();
        if (threadIdx.x < FH) {
            int f = threadIdx.x;
            int g0 = sg[0];
            bool uni = true;
            #pragma unroll
            for (int q = 1; q < 8; q++) uni &= (sg[q] == g0);
            if (uni) {
                float ssum = 0.f;
                #pragma unroll
                for (int q = 0; q < 8; q++) ssum += sv[q][f];
                atomicAdd(&g_pool[g0 * FH + f], ssum);
            } else {
                #pragma unroll
                for (int q = 0; q < 8; q++)
                    atomicAdd(&g_pool[sg[q] * FH + f], sv[q][f]);
            }
        }
    }
}

// ---------------- final: mean pool -> [NG, NCLS]; re-zero pool -------------
__global__ void k_final(const float* __restrict__ Wlin, const float* __restrict__ blin,
                        float* __restrict__ out) {
    __shared__ float p[FH];
    int g = blockIdx.x, tid = threadIdx.x;
    float cnt = fmaxf((float)(g_bnd[g + 1] - g_bnd[g]), 1.0f);
    p[tid] = g_pool[g * FH + tid] / cnt;
    g_pool[g * FH + tid] = 0.f;           // re-arm invariant for next call
    __syncthreads();
    if (tid < NCLS) {
        float s = blin[tid];
        #pragma unroll 8
        for (int f = 0; f < FH; f++) s = fmaf(p[f], Wlin[f * NCLS + tid], s);
        out[g * NCLS + tid] = s;
    }
}

// ---------------- launch ----------------
extern "C" void kernel_launch(void* const* d_in, const int* in_sizes, int n_in,
                              void* d_out, int out_size) {
    const float* x      = (const float*)d_in[0];
    const void*  ei     = d_in[1];
    const void*  batch  = d_in[2];
    const float* W1     = (const float*)d_in[3];
    const float* a_src1 = (const float*)d_in[4];
    const float* a_dst1 = (const float*)d_in[5];
    const float* b1     = (const float*)d_in[6];
    const float* W2     = (const float*)d_in[7];
    const float* a_src2 = (const float*)d_in[8];
    const float* a_dst2 = (const float*)d_in[9];
    const float* b2     = (const float*)d_in[10];
    const float* Wlin   = (const float*)d_in[11];
    const float* blin   = (const float*)d_in[12];
    float* out = (float*)d_out;

    // layer-1 linear + fused degree histogram (g_deg zero on entry)
    k_lin<FIN, 0, 1><<<(NN + 31) / 32, 128>>>(x, W1, a_src1, a_dst1, ei, batch);
    k_scan   <<<NBLK, 256>>>();
    k_scatter<<<(ST + 255) / 256, 256>>>(ei);
    k_gat<1> <<<NN / 8, 256>>>(b1, batch, ei);

    // layer-2 linear + fused boundary marking, gather + fused mean-pool
    k_lin<FH, 1, 2><<<(NN + 31) / 32, 128>>>(x, W2, a_src2, a_dst2, ei, batch);
    k_gat<2> <<<NN / 8, 256>>>(b2, batch, ei);

    // classifier head
    k_final  <<<NG, FH>>>(Wlin, blin, out);
}

// round 13
// speedup vs baseline: 1.0439x; 1.0439x over previous
#include <cuda_runtime.h>
#include <cuda_bf16.h>
#include <cuda_fp16.h>

#define NN      50000
#define EE      800000
#define ET      (EE + NN)      // edges incl. self loops
#define NG      512
#define FIN     128
#define FH      64
#define NCLS    10
#define NEGS    0.2f
#define EPSV    1e-16f
#define NBLK    ((NN + 255) / 256)   // 196 scan blocks

// ---------------- device scratch (no allocations allowed) ----------------
// INVARIANT: g_deg and g_pool are all-zero at every kernel_launch entry.
// (zero at module load; k_scatter re-zeroes g_deg, k_final re-zeroes g_pool.)
__device__ __half g_h[NN * FH];       // pre-aggregation features (fp16 gather payload)
__device__ float  g_x2[NN * FH];      // layer-1 output / layer-2 input
__device__ float  g_as[NN];           // alpha_src per node (current layer)
__device__ float  g_ad[NN];           // alpha_dst per node (current layer)
__device__ int    g_deg[NN];          // real in-degree only (self loop added in scan)
__device__ int    g_off[NN + 1];
__device__ int    g_cur[NN];
__device__ float2 g_cse[ET];          // CSR slot: (src id bit-cast, as1[src])
__device__ float  g_pool[NG * FH];
__device__ int    g_bnd[NG + 1];

// per-warp dtype detection from edge_index (values < NN; int32 data read as
// int64 yields huge values from packed pairs). batch can't be used: sorted,
// starts at 0, would false-positive as int64.
__device__ __forceinline__ int warp_is64(const void* ei) {
    const long long* p = (const long long*)ei;
    long long v = p[threadIdx.x & 31];
    int bad = (v < 0 || v >= NN);
    return (__ballot_sync(0xffffffffu, bad) == 0u);
}
__device__ __forceinline__ int ld_idx(const void* p, long i, int is64) {
    if (is64) return (int)((const long long*)p)[i];
    return ((const int*)p)[i];
}

// ---- packed f32x2 helpers (Blackwell FFMA2: 2x fp32 throughput) ----
__device__ __forceinline__ void ffma2(unsigned long long& acc,
                                      unsigned long long a, unsigned long long b) {
    asm("fma.rn.f32x2 %0, %1, %2, %0;" : "+l"(acc) : "l"(a), "l"(b));
}
__device__ __forceinline__ void upk(unsigned long long r, float& a, float& b) {
    asm("mov.b64 {%0,%1}, %2;" : "=f"(a), "=f"(b) : "l"(r));
}

// ---------------- merged exclusive scan of (deg+1) -------------------------
// Each block sums g_deg over [0, blk*256) itself (coalesced, L2-resident,
// fully parallel across blocks). g_deg NOT zeroed here (cross-block reads).
__global__ void k_scan() {
    __shared__ int ws[8];
    __shared__ int boff_s;
    int tid = threadIdx.x, lane = tid & 31, wid = tid >> 5;
    int pre = blockIdx.x * 256;       // elements before this block

    int a0 = 0, a1 = 0, a2 = 0, a3 = 0;
    int j = tid;
    for (; j + 768 < pre; j += 1024) {
        a0 += g_deg[j];
        a1 += g_deg[j + 256];
        a2 += g_deg[j + 512];
        a3 += g_deg[j + 768];
    }
    for (; j < pre; j += 256) a0 += g_deg[j];
    int acc = (a0 + a1) + (a2 + a3);
    #pragma unroll
    for (int off = 16; off > 0; off >>= 1) acc += __shfl_xor_sync(0xffffffffu, acc, off);
    if (lane == 0) ws[wid] = acc;
    __syncthreads();
    if (tid == 0) {
        int s = 0;
        #pragma unroll
        for (int q = 0; q < 8; q++) s += ws[q];
        boff_s = s + pre;             // + pre accounts for the +1 self loop each
    }
    __syncthreads();
    int boff = boff_s;
    __syncthreads();                  // ws reused below

    int i = pre + tid;
    int v = (i < NN) ? (g_deg[i] + 1) : 0;
    int val = v;
    #pragma unroll
    for (int off = 1; off < 32; off <<= 1) {
        int t = __shfl_up_sync(0xffffffffu, val, off);
        if (lane >= off) val += t;
    }
    if (lane == 31) ws[wid] = val;
    __syncthreads();
    if (wid == 0 && lane < 8) {
        int s = ws[lane];
        #pragma unroll
        for (int off = 1; off < 8; off <<= 1) {
            int t = __shfl_up_sync(0xffu, s, off);
            if (lane >= off) s += t;
        }
        ws[lane] = s;
    }
    __syncthreads();
    int woff = (wid > 0) ? ws[wid - 1] : 0;
    int excl = val - v + woff + boff;
    if (i < NN) { g_off[i] = excl; g_cur[i] = excl; }
    if (i == NN - 1) g_off[NN] = ET;
}

// ---------------- scatter edges (+self loops) into CSR ---------------------
// Runs AFTER k_lin1, so as1 is available: stores (src, as1[src]) per slot,
// collapsing gat1's dependent random-load chain into one coalesced load.
// Phase-split for MLP; also re-zeroes g_deg.
#define ST ((ET + 3) / 4)      // 212513; quarters tile exactly with guard
__global__ void k_scatter(const void* __restrict__ ei) {
    int is64 = warp_is64(ei);
    int t = blockIdx.x * blockDim.x + threadIdx.x;
    if (t >= ST) return;
    if (t < NN) g_deg[t] = 0;         // re-arm invariant for next call

    int d[4], s[4];
    bool ok[4];
    #pragma unroll
    for (int q = 0; q < 4; q++) {     // batch loads (independent)
        int i = t + q * ST;
        ok[q] = (i < ET);
        d[q] = 0; s[q] = 0;
        if (i < EE) {
            d[q] = ld_idx(ei, (long)EE + i, is64);
            s[q] = ld_idx(ei, i, is64);
        } else if (i < ET) {
            d[q] = i - EE;
            s[q] = i - EE;
        }
    }
    float av[4];
    #pragma unroll
    for (int q = 0; q < 4; q++)       // batch as1 gathers (independent)
        av[q] = ok[q] ? g_as[s[q]] : 0.f;
    int pos[4];
    #pragma unroll
    for (int q = 0; q < 4; q++)       // batch atomics (pipeline)
        if (ok[q]) pos[q] = atomicAdd(&g_cur[d[q]], 1);
    #pragma unroll
    for (int q = 0; q < 4; q++)       // batch stores
        if (ok[q]) g_cse[pos[q]] = make_float2(__int_as_float(s[q]), av[q]);
}

// ---------------- linear: g_h = x @ W ; g_as = h.a_src ; g_ad = h.a_dst ----
// Compute fp32 (f32x2 packed FMAs); store h as fp16 for the gather.
// XTRA==1: also histogram edge in-degrees (fire-and-forget REDs hide under GEMM).
// XTRA==2: also mark graph boundaries from sorted batch.
template <int K, int SRC, int XTRA>
__global__ void __launch_bounds__(128) k_lin(const float* __restrict__ x,
                                             const float* __restrict__ W,
                                             const float* __restrict__ a_s,
                                             const float* __restrict__ a_d,
                                             const void* __restrict__ ei,
                                             const void* __restrict__ batch) {
    constexpr int KP = K + 4;                 // pad: (c*KP) % 32 walks banks
    __shared__ float Wt[FH * KP];             // W transposed: Wt[c][k]
    __shared__ float xs[32 * K];
    int tid = threadIdx.x;

    if (XTRA == 1) {                  // fused degree histogram (512 edges/block)
        int is64 = warp_is64(ei);
        int ebase = blockIdx.x * 512;
        #pragma unroll
        for (int q = 0; q < 4; q++) {
            int e = ebase + tid + q * 128;
            if (e < EE) {
                int dd = ld_idx(ei, (long)EE + e, is64);
                atomicAdd(&g_deg[dd], 1);     // no return use -> RED
            }
        }
    }
    if (XTRA == 2) {                  // fused graph-boundary marking
        int is64 = warp_is64(ei);
        int i = blockIdx.x * 128 + tid;
        if (i < NN) {
            int b  = ld_idx(batch, i, is64);
            int bp = (i == 0) ? -1 : ld_idx(batch, i - 1, is64);
            for (int g = bp + 1; g <= b; g++) g_bnd[g] = i;
            if (i == NN - 1)
                for (int g = b + 1; g <= NG; g++) g_bnd[g] = NN;
        }
    }

    for (int i = tid; i < K * FH; i += 128) {
        int k = i / FH, c = i % FH;
        Wt[c * KP + k] = W[i];
    }
    int base = blockIdx.x * 32;
    const float* xin = (SRC == 0) ? x : (const float*)g_x2;
    for (int i = tid; i < 32 * K; i += 128) {
        int n = i / K;
        int node = base + n;
        xs[i] = (node < NN) ? xin[(size_t)node * K + (i % K)] : 0.f;
    }
    __syncthreads();

    int c = tid & 31;       // output cols c and c+32
    int w = tid >> 5;       // warp handles nodes base + w*8 .. +7

    unsigned long long accA[8][2], accB[8][2];
    #pragma unroll
    for (int n = 0; n < 8; n++) {
        accA[n][0] = accA[n][1] = 0ull;
        accB[n][0] = accB[n][1] = 0ull;
    }

    const ulonglong2* wrowA = (const ulonglong2*)(Wt + c * KP);
    const ulonglong2* wrowB = (const ulonglong2*)(Wt + (c + 32) * KP);
    const ulonglong2* xrow  = (const ulonglong2*)(xs + (w * 8) * K);

    #pragma unroll 4
    for (int k4 = 0; k4 < K / 4; k4++) {
        ulonglong2 wa = wrowA[k4];
        ulonglong2 wb = wrowB[k4];
        #pragma unroll
        for (int n = 0; n < 8; n++) {
            ulonglong2 xv = xrow[n * (K / 4) + k4];   // broadcast across lanes
            ffma2(accA[n][0], xv.x, wa.x);
            ffma2(accA[n][1], xv.y, wa.y);
            ffma2(accB[n][0], xv.x, wb.x);
            ffma2(accB[n][1], xv.y, wb.y);
        }
    }

    float as0 = a_s[c], as1 = a_s[32 + c];
    float ad0 = a_d[c], ad1 = a_d[32 + c];
    #pragma unroll
    for (int n = 0; n < 8; n++) {
        int node = base + w * 8 + n;
        float p0, p1, p2, p3;
        upk(accA[n][0], p0, p1); upk(accA[n][1], p2, p3);
        float h0 = (p0 + p1) + (p2 + p3);
        upk(accB[n][0], p0, p1); upk(accB[n][1], p2, p3);
        float h1 = (p0 + p1) + (p2 + p3);
        if (node < NN) {
            g_h[node * FH + c]      = __float2half_rn(h0);
            g_h[node * FH + 32 + c] = __float2half_rn(h1);
        }
        float s = h0 * as0 + h1 * as1;
        float d = h0 * ad0 + h1 * ad1;
        #pragma unroll
        for (int off = 16; off > 0; off >>= 1) {
            s += __shfl_xor_sync(0xffffffffu, s, off);
            d += __shfl_xor_sync(0xffffffffu, d, off);
        }
        if (c == 0 && node < NN) { g_as[node] = s; g_ad[node] = d; }
    }
}

// ---------------- GAT gather: warp per node, single pass -------------------
// exp without max-subtraction: logits O(+-10), safe in fp32, identical math:
// out = sum(e_i*h_i) / (sum e_i + EPS).
// LAYER 1: alpha_src comes packed in g_cse (coalesced, no dependent load).
// LAYER 2: alpha_src gathered from g_as (random; as2 unknown at scatter time).
template <int LAYER>
__global__ void __launch_bounds__(256, 8) k_gat(const float* __restrict__ b,
                                                const void* __restrict__ batch,
                                                const void* __restrict__ ei) {
    int lane = threadIdx.x & 31;
    int w = threadIdx.x >> 5;
    int node = blockIdx.x * 8 + w;        // NN % 8 == 0
    int beg = g_off[node];
    int end = g_off[node + 1];
    float adv = g_ad[node];

    const __half2* h2 = (const __half2*)g_h;
    float2 acc = make_float2(0.f, 0.f);
    float esum = 0.f;
    for (int cb = beg; cb < end; cb += 32) {
        int i = cb + lane;
        float2 cs = make_float2(0.f, 0.f);
        if (i < end) cs = g_cse[i];
        int s = __float_as_int(cs.x);
        float e = 0.f;
        if (i < end) {
            float asv = (LAYER == 1) ? cs.y : g_as[s];
            float l = asv + adv;
            l = (l > 0.f) ? l : NEGS * l;
            e = __expf(l);
        }
        esum += e;
        int cnt = min(32, end - cb);
        int j = 0;
        for (; j + 4 <= cnt; j += 4) {
            float wj[4]; int sj[4]; float2 hv[4];
            #pragma unroll
            for (int q = 0; q < 4; q++) {
                wj[q] = __shfl_sync(0xffffffffu, e, j + q);
                sj[q] = __shfl_sync(0xffffffffu, s, j + q);
            }
            #pragma unroll
            for (int q = 0; q < 4; q++)
                hv[q] = __half22float2(h2[sj[q] * 32 + lane]);
            #pragma unroll
            for (int q = 0; q < 4; q++) {
                acc.x = fmaf(wj[q], hv[q].x, acc.x);
                acc.y = fmaf(wj[q], hv[q].y, acc.y);
            }
        }
        for (; j < cnt; j++) {
            float wj = __shfl_sync(0xffffffffu, e, j);
            int   sj = __shfl_sync(0xffffffffu, s, j);
            float2 hv = __half22float2(h2[sj * 32 + lane]);
            acc.x = fmaf(wj, hv.x, acc.x);
            acc.y = fmaf(wj, hv.y, acc.y);
        }
    }
    #pragma unroll
    for (int off = 16; off > 0; off >>= 1)
        esum += __shfl_xor_sync(0xffffffffu, esum, off);
    float inv = 1.f / (esum + EPSV);

    float v0 = acc.x * inv + b[2 * lane];
    float v1 = acc.y * inv + b[2 * lane + 1];

    if (LAYER == 1) {
        v0 = fmaxf(v0, 0.f);
        v1 = fmaxf(v1, 0.f);
        ((float2*)g_x2)[node * 32 + lane] = make_float2(v0, v1);
    } else {
        int is64 = warp_is64(ei);
        __shared__ float sv[8][FH];
        __shared__ int sg[8];
        sv[w][2 * lane]     = v0;
        sv[w][2 * lane + 1] = v1;
        if (lane == 0) sg[w] = ld_idx(batch, node, is64);
        __syncthreads();
        if (threadIdx.x < FH) {
            int f = threadIdx.x;
            int g0 = sg[0];
            bool uni = true;
            #pragma unroll
            for (int q = 1; q < 8; q++) uni &= (sg[q] == g0);
            if (uni) {
                float ssum = 0.f;
                #pragma unroll
                for (int q = 0; q < 8; q++) ssum += sv[q][f];
                atomicAdd(&g_pool[g0 * FH + f], ssum);
            } else {
                #pragma unroll
                for (int q = 0; q < 8; q++)
                    atomicAdd(&g_pool[sg[q] * FH + f], sv[q][f]);
            }
        }
    }
}

// ---------------- final: mean pool -> [NG, NCLS]; re-zero pool -------------
__global__ void k_final(const float* __restrict__ Wlin, const float* __restrict__ blin,
                        float* __restrict__ out) {
    __shared__ float p[FH];
    int g = blockIdx.x, tid = threadIdx.x;
    float cnt = fmaxf((float)(g_bnd[g + 1] - g_bnd[g]), 1.0f);
    p[tid] = g_pool[g * FH + tid] / cnt;
    g_pool[g * FH + tid] = 0.f;           // re-arm invariant for next call
    __syncthreads();
    if (tid < NCLS) {
        float s = blin[tid];
        #pragma unroll 8
        for (int f = 0; f < FH; f++) s = fmaf(p[f], Wlin[f * NCLS + tid], s);
        out[g * NCLS + tid] = s;
    }
}

// ---------------- launch ----------------
extern "C" void kernel_launch(void* const* d_in, const int* in_sizes, int n_in,
                              void* d_out, int out_size) {
    const float* x      = (const float*)d_in[0];
    const void*  ei     = d_in[1];
    const void*  batch  = d_in[2];
    const float* W1     = (const float*)d_in[3];
    const float* a_src1 = (const float*)d_in[4];
    const float* a_dst1 = (const float*)d_in[5];
    const float* b1     = (const float*)d_in[6];
    const float* W2     = (const float*)d_in[7];
    const float* a_src2 = (const float*)d_in[8];
    const float* a_dst2 = (const float*)d_in[9];
    const float* b2     = (const float*)d_in[10];
    const float* Wlin   = (const float*)d_in[11];
    const float* blin   = (const float*)d_in[12];
    float* out = (float*)d_out;

    // layer-1 linear + fused degree histogram (g_deg zero on entry)
    k_lin<FIN, 0, 1><<<(NN + 31) / 32, 128>>>(x, W1, a_src1, a_dst1, ei, batch);
    k_scan   <<<NBLK, 256>>>();
    k_scatter<<<(ST + 255) / 256, 256>>>(ei);   // packs (src, as1[src])
    k_gat<1> <<<NN / 8, 256>>>(b1, batch, ei);

    // layer-2 linear + fused boundary marking, gather + fused mean-pool
    k_lin<FH, 1, 2><<<(NN + 31) / 32, 128>>>(x, W2, a_src2, a_dst2, ei, batch);
    k_gat<2> <<<NN / 8, 256>>>(b2, batch, ei);

    // classifier head
    k_final  <<<NG, FH>>>(Wlin, blin, out);
}

// round 14
// speedup vs baseline: 1.0742x; 1.0290x over previous
#include <cuda_runtime.h>
#include <cuda_bf16.h>
#include <cuda_fp16.h>

#define NN      50000
#define EE      800000
#define ET      (EE + NN)      // edges incl. self loops
#define NG      512
#define FIN     128
#define FH      64
#define NCLS    10
#define NEGS    0.2f
#define EPSV    1e-16f
#define NBLK    ((NN + 255) / 256)   // 196 scan blocks

// ---------------- device scratch (no allocations allowed) ----------------
// INVARIANT: g_deg and g_pool are all-zero at every kernel_launch entry.
// (zero at module load; k_scatter re-zeroes g_deg, k_final re-zeroes g_pool.)
__device__ __half g_h[NN * FH];       // pre-aggregation features (fp16 gather payload)
__device__ float  g_x2[NN * FH];      // layer-1 output / layer-2 input
__device__ float  g_as[NN];           // alpha_src per node (current layer)
__device__ float  g_ad[NN];           // alpha_dst per node (current layer)
__device__ int    g_deg[NN];          // real in-degree only (self loop added in scan)
__device__ int    g_off[NN + 1];
__device__ int    g_cur[NN];
__device__ float2 g_cse[ET];          // CSR slot: (src id bit-cast, as1[src])
__device__ float  g_pool[NG * FH];
__device__ int    g_bnd[NG + 1];

// per-warp dtype detection from edge_index (values < NN; int32 data read as
// int64 yields huge values from packed pairs). batch can't be used: sorted,
// starts at 0, would false-positive as int64.
__device__ __forceinline__ int warp_is64(const void* ei) {
    const long long* p = (const long long*)ei;
    long long v = p[threadIdx.x & 31];
    int bad = (v < 0 || v >= NN);
    return (__ballot_sync(0xffffffffu, bad) == 0u);
}
__device__ __forceinline__ int ld_idx(const void* p, long i, int is64) {
    if (is64) return (int)((const long long*)p)[i];
    return ((const int*)p)[i];
}

// ---- packed f32x2 helpers (Blackwell FFMA2: 2x fp32 throughput) ----
__device__ __forceinline__ void ffma2(unsigned long long& acc,
                                      unsigned long long a, unsigned long long b) {
    asm("fma.rn.f32x2 %0, %1, %2, %0;" : "+l"(acc) : "l"(a), "l"(b));
}
__device__ __forceinline__ void upk(unsigned long long r, float& a, float& b) {
    asm("mov.b64 {%0,%1}, %2;" : "=f"(a), "=f"(b) : "l"(r));
}

// ---------------- merged exclusive scan of (deg+1) -------------------------
__global__ void k_scan() {
    __shared__ int ws[8];
    __shared__ int boff_s;
    int tid = threadIdx.x, lane = tid & 31, wid = tid >> 5;
    int pre = blockIdx.x * 256;       // elements before this block

    int a0 = 0, a1 = 0, a2 = 0, a3 = 0;
    int j = tid;
    for (; j + 768 < pre; j += 1024) {
        a0 += g_deg[j];
        a1 += g_deg[j + 256];
        a2 += g_deg[j + 512];
        a3 += g_deg[j + 768];
    }
    for (; j < pre; j += 256) a0 += g_deg[j];
    int acc = (a0 + a1) + (a2 + a3);
    #pragma unroll
    for (int off = 16; off > 0; off >>= 1) acc += __shfl_xor_sync(0xffffffffu, acc, off);
    if (lane == 0) ws[wid] = acc;
    __syncthreads();
    if (tid == 0) {
        int s = 0;
        #pragma unroll
        for (int q = 0; q < 8; q++) s += ws[q];
        boff_s = s + pre;             // + pre accounts for the +1 self loop each
    }
    __syncthreads();
    int boff = boff_s;
    __syncthreads();                  // ws reused below

    int i = pre + tid;
    int v = (i < NN) ? (g_deg[i] + 1) : 0;
    int val = v;
    #pragma unroll
    for (int off = 1; off < 32; off <<= 1) {
        int t = __shfl_up_sync(0xffffffffu, val, off);
        if (lane >= off) val += t;
    }
    if (lane == 31) ws[wid] = val;
    __syncthreads();
    if (wid == 0 && lane < 8) {
        int s = ws[lane];
        #pragma unroll
        for (int off = 1; off < 8; off <<= 1) {
            int t = __shfl_up_sync(0xffu, s, off);
            if (lane >= off) s += t;
        }
        ws[lane] = s;
    }
    __syncthreads();
    int woff = (wid > 0) ? ws[wid - 1] : 0;
    int excl = val - v + woff + boff;
    if (i < NN) { g_off[i] = excl; g_cur[i] = excl; }
    if (i == NN - 1) g_off[NN] = ET;
}

// ---------------- scatter edges (+self loops) into CSR ---------------------
// Runs AFTER k_lin1: stores (src, as1[src]) per slot. Phase-split for MLP.
#define ST ((ET + 3) / 4)      // 212513; quarters tile exactly with guard
__global__ void k_scatter(const void* __restrict__ ei) {
    int is64 = warp_is64(ei);
    int t = blockIdx.x * blockDim.x + threadIdx.x;
    if (t >= ST) return;
    if (t < NN) g_deg[t] = 0;         // re-arm invariant for next call

    int d[4], s[4];
    bool ok[4];
    #pragma unroll
    for (int q = 0; q < 4; q++) {     // batch loads (independent)
        int i = t + q * ST;
        ok[q] = (i < ET);
        d[q] = 0; s[q] = 0;
        if (i < EE) {
            d[q] = ld_idx(ei, (long)EE + i, is64);
            s[q] = ld_idx(ei, i, is64);
        } else if (i < ET) {
            d[q] = i - EE;
            s[q] = i - EE;
        }
    }
    float av[4];
    #pragma unroll
    for (int q = 0; q < 4; q++)       // batch as1 gathers (independent)
        av[q] = ok[q] ? g_as[s[q]] : 0.f;
    int pos[4];
    #pragma unroll
    for (int q = 0; q < 4; q++)       // batch atomics (pipeline)
        if (ok[q]) pos[q] = atomicAdd(&g_cur[d[q]], 1);
    #pragma unroll
    for (int q = 0; q < 4; q++)       // batch stores
        if (ok[q]) g_cse[pos[q]] = make_float2(__int_as_float(s[q]), av[q]);
}

// ---------------- linear: g_h = x @ W ; g_as = h.a_src ; g_ad = h.a_dst ----
// XTRA==1: fused degree histogram. XTRA==2: fused graph-boundary marking.
template <int K, int SRC, int XTRA>
__global__ void __launch_bounds__(128) k_lin(const float* __restrict__ x,
                                             const float* __restrict__ W,
                                             const float* __restrict__ a_s,
                                             const float* __restrict__ a_d,
                                             const void* __restrict__ ei,
                                             const void* __restrict__ batch) {
    constexpr int KP = K + 4;                 // pad: (c*KP) % 32 walks banks
    __shared__ float Wt[FH * KP];             // W transposed: Wt[c][k]
    __shared__ float xs[32 * K];
    int tid = threadIdx.x;

    if (XTRA == 1) {                  // fused degree histogram (512 edges/block)
        int is64 = warp_is64(ei);
        int ebase = blockIdx.x * 512;
        #pragma unroll
        for (int q = 0; q < 4; q++) {
            int e = ebase + tid + q * 128;
            if (e < EE) {
                int dd = ld_idx(ei, (long)EE + e, is64);
                atomicAdd(&g_deg[dd], 1);     // no return use -> RED
            }
        }
    }
    if (XTRA == 2) {                  // fused graph-boundary marking
        int is64 = warp_is64(ei);
        int i = blockIdx.x * 128 + tid;
        if (i < NN) {
            int b  = ld_idx(batch, i, is64);
            int bp = (i == 0) ? -1 : ld_idx(batch, i - 1, is64);
            for (int g = bp + 1; g <= b; g++) g_bnd[g] = i;
            if (i == NN - 1)
                for (int g = b + 1; g <= NG; g++) g_bnd[g] = NN;
        }
    }

    for (int i = tid; i < K * FH; i += 128) {
        int k = i / FH, c = i % FH;
        Wt[c * KP + k] = W[i];
    }
    int base = blockIdx.x * 32;
    const float* xin = (SRC == 0) ? x : (const float*)g_x2;
    for (int i = tid; i < 32 * K; i += 128) {
        int n = i / K;
        int node = base + n;
        xs[i] = (node < NN) ? xin[(size_t)node * K + (i % K)] : 0.f;
    }
    __syncthreads();

    int c = tid & 31;       // output cols c and c+32
    int w = tid >> 5;       // warp handles nodes base + w*8 .. +7

    unsigned long long accA[8][2], accB[8][2];
    #pragma unroll
    for (int n = 0; n < 8; n++) {
        accA[n][0] = accA[n][1] = 0ull;
        accB[n][0] = accB[n][1] = 0ull;
    }

    const ulonglong2* wrowA = (const ulonglong2*)(Wt + c * KP);
    const ulonglong2* wrowB = (const ulonglong2*)(Wt + (c + 32) * KP);
    const ulonglong2* xrow  = (const ulonglong2*)(xs + (w * 8) * K);

    #pragma unroll 4
    for (int k4 = 0; k4 < K / 4; k4++) {
        ulonglong2 wa = wrowA[k4];
        ulonglong2 wb = wrowB[k4];
        #pragma unroll
        for (int n = 0; n < 8; n++) {
            ulonglong2 xv = xrow[n * (K / 4) + k4];   // broadcast across lanes
            ffma2(accA[n][0], xv.x, wa.x);
            ffma2(accA[n][1], xv.y, wa.y);
            ffma2(accB[n][0], xv.x, wb.x);
            ffma2(accB[n][1], xv.y, wb.y);
        }
    }

    float as0 = a_s[c], as1 = a_s[32 + c];
    float ad0 = a_d[c], ad1 = a_d[32 + c];
    #pragma unroll
    for (int n = 0; n < 8; n++) {
        int node = base + w * 8 + n;
        float p0, p1, p2, p3;
        upk(accA[n][0], p0, p1); upk(accA[n][1], p2, p3);
        float h0 = (p0 + p1) + (p2 + p3);
        upk(accB[n][0], p0, p1); upk(accB[n][1], p2, p3);
        float h1 = (p0 + p1) + (p2 + p3);
        if (node < NN) {
            g_h[node * FH + c]      = __float2half_rn(h0);
            g_h[node * FH + 32 + c] = __float2half_rn(h1);
        }
        float s = h0 * as0 + h1 * as1;
        float d = h0 * ad0 + h1 * ad1;
        #pragma unroll
        for (int off = 16; off > 0; off >>= 1) {
            s += __shfl_xor_sync(0xffffffffu, s, off);
            d += __shfl_xor_sync(0xffffffffu, d, off);
        }
        if (c == 0 && node < NN) { g_as[node] = s; g_ad[node] = d; }
    }
}

// ---------------- GAT gather: warp per node, 4 edges/iteration -------------
// Lane l serves edge j+(l>>3) and loads uint4 = 8 fp16 features of that edge's
// h row. 2 SHFLs + 1 LDG.128 cover 4 edges. acc[8] per lane = features
// (l&7)*8..+7; reduced across the 4 edge-groups at the end (xor 8, 16).
// Tail: clamp shuffle selector, zero weight (valid row read, 0 contribution).
// exp w/o max-subtraction: logits O(+-10), fp32-safe, identical math.
template <int LAYER>
__global__ void __launch_bounds__(256) k_gat(const float* __restrict__ b,
                                             const void* __restrict__ batch,
                                             const void* __restrict__ ei) {
    int lane = threadIdx.x & 31;
    int w = threadIdx.x >> 5;
    int node = blockIdx.x * 8 + w;        // NN % 8 == 0
    int beg = g_off[node];
    int end = g_off[node + 1];
    float adv = g_ad[node];
    int grp = lane >> 3;                  // which edge of the group of 4
    int sub = lane & 7;                   // which 16B chunk of the h row

    const uint4* h4 = (const uint4*)g_h;  // 8 uint4 per row
    float acc[8];
    #pragma unroll
    for (int k = 0; k < 8; k++) acc[k] = 0.f;
    float esum = 0.f;

    for (int cb = beg; cb < end; cb += 32) {
        int i = cb + lane;
        float2 cs = make_float2(0.f, 0.f);
        if (i < end) cs = g_cse[i];
        int s = __float_as_int(cs.x);
        float e = 0.f;
        if (i < end) {
            float asv = (LAYER == 1) ? cs.y : g_as[s];
            float l = asv + adv;
            l = (l > 0.f) ? l : NEGS * l;
            e = __expf(l);
        }
        esum += e;
        int cnt = min(32, end - cb);
        for (int j = 0; j < cnt; j += 4) {
            int ii = j + grp;
            int sel = (ii < cnt) ? ii : 0;
            float wgt = __shfl_sync(0xffffffffu, e, sel);
            int   sj  = __shfl_sync(0xffffffffu, s, sel);
            if (ii >= cnt) wgt = 0.f;
            uint4 r = h4[sj * 8 + sub];
            __half2* hp = (__half2*)&r;
            #pragma unroll
            for (int k = 0; k < 4; k++) {
                float2 f = __half22float2(hp[k]);
                acc[2 * k]     = fmaf(wgt, f.x, acc[2 * k]);
                acc[2 * k + 1] = fmaf(wgt, f.y, acc[2 * k + 1]);
            }
        }
    }
    #pragma unroll
    for (int off = 16; off > 0; off >>= 1)
        esum += __shfl_xor_sync(0xffffffffu, esum, off);
    #pragma unroll
    for (int k = 0; k < 8; k++) {
        acc[k] += __shfl_xor_sync(0xffffffffu, acc[k], 8);
        acc[k] += __shfl_xor_sync(0xffffffffu, acc[k], 16);
    }
    float inv = 1.f / (esum + EPSV);

    if (LAYER == 1) {
        if (lane < 8) {
            const float4* b4 = (const float4*)b;
            float4 bv0 = b4[sub * 2], bv1 = b4[sub * 2 + 1];
            float4 o0, o1;
            o0.x = fmaxf(acc[0] * inv + bv0.x, 0.f);
            o0.y = fmaxf(acc[1] * inv + bv0.y, 0.f);
            o0.z = fmaxf(acc[2] * inv + bv0.z, 0.f);
            o0.w = fmaxf(acc[3] * inv + bv0.w, 0.f);
            o1.x = fmaxf(acc[4] * inv + bv1.x, 0.f);
            o1.y = fmaxf(acc[5] * inv + bv1.y, 0.f);
            o1.z = fmaxf(acc[6] * inv + bv1.z, 0.f);
            o1.w = fmaxf(acc[7] * inv + bv1.w, 0.f);
            float4* x4 = (float4*)g_x2;
            x4[node * 16 + sub * 2]     = o0;
            x4[node * 16 + sub * 2 + 1] = o1;
        }
    } else {
        int is64 = warp_is64(ei);
        __shared__ float sv[8][FH];
        __shared__ int sg[8];
        if (lane < 8) {
            #pragma unroll
            for (int k = 0; k < 8; k++)
                sv[w][sub * 8 + k] = acc[k] * inv + b[sub * 8 + k];
        }
        if (lane == 0) sg[w] = ld_idx(batch, node, is64);
        __syncthreads();
        if (threadIdx.x < FH) {
            int f = threadIdx.x;
            int g0 = sg[0];
            bool uni = true;
            #pragma unroll
            for (int q = 1; q < 8; q++) uni &= (sg[q] == g0);
            if (uni) {
                float ssum = 0.f;
                #pragma unroll
                for (int q = 0; q < 8; q++) ssum += sv[q][f];
                atomicAdd(&g_pool[g0 * FH + f], ssum);
            } else {
                #pragma unroll
                for (int q = 0; q < 8; q++)
                    atomicAdd(&g_pool[sg[q] * FH + f], sv[q][f]);
            }
        }
    }
}

// ---------------- final: mean pool -> [NG, NCLS]; re-zero pool -------------
__global__ void k_final(const float* __restrict__ Wlin, const float* __restrict__ blin,
                        float* __restrict__ out) {
    __shared__ float p[FH];
    int g = blockIdx.x, tid = threadIdx.x;
    float cnt = fmaxf((float)(g_bnd[g + 1] - g_bnd[g]), 1.0f);
    p[tid] = g_pool[g * FH + tid] / cnt;
    g_pool[g * FH + tid] = 0.f;           // re-arm invariant for next call
    __syncthreads();
    if (tid < NCLS) {
        float s = blin[tid];
        #pragma unroll 8
        for (int f = 0; f < FH; f++) s = fmaf(p[f], Wlin[f * NCLS + tid], s);
        out[g * NCLS + tid] = s;
    }
}

// ---------------- launch ----------------
extern "C" void kernel_launch(void* const* d_in, const int* in_sizes, int n_in,
                              void* d_out, int out_size) {
    const float* x      = (const float*)d_in[0];
    const void*  ei     = d_in[1];
    const void*  batch  = d_in[2];
    const float* W1     = (const float*)d_in[3];
    const float* a_src1 = (const float*)d_in[4];
    const float* a_dst1 = (const float*)d_in[5];
    const float* b1     = (const float*)d_in[6];
    const float* W2     = (const float*)d_in[7];
    const float* a_src2 = (const float*)d_in[8];
    const float* a_dst2 = (const float*)d_in[9];
    const float* b2     = (const float*)d_in[10];
    const float* Wlin   = (const float*)d_in[11];
    const float* blin   = (const float*)d_in[12];
    float* out = (float*)d_out;

    // layer-1 linear + fused degree histogram (g_deg zero on entry)
    k_lin<FIN, 0, 1><<<(NN + 31) / 32, 128>>>(x, W1, a_src1, a_dst1, ei, batch);
    k_scan   <<<NBLK, 256>>>();
    k_scatter<<<(ST + 255) / 256, 256>>>(ei);   // packs (src, as1[src])
    k_gat<1> <<<NN / 8, 256>>>(b1, batch, ei);

    // layer-2 linear + fused boundary marking, gather + fused mean-pool
    k_lin<FH, 1, 2><<<(NN + 31) / 32, 128>>>(x, W2, a_src2, a_dst2, ei, batch);
    k_gat<2> <<<NN / 8, 256>>>(b2, batch, ei);

    // classifier head
    k_final  <<<NG, FH>>>(Wlin, blin, out);
}